// round 1
// baseline (speedup 1.0000x reference)
#include <cuda_runtime.h>
#include <cuda_bf16.h>

#define BATCH 64
#define SEQT  80
#define EMBD  100
#define UN    2048
#define NCTA  128
#define NTHR  256
#define CK    128
#define CPB   16          // output columns per CTA (per GEMM)
#define HS_STRIDE 128     // smem stride for h chunk rows
#define WS_STRIDE 130     // smem stride for transposed W chunk (even, conflict-free)

typedef unsigned long long ull;

// Persistent state (allocation-free scratch)
__device__ float g_h0[2][BATCH * UN];
__device__ float g_h1[2][BATCH * UN];
__device__ unsigned int g_bar;

#define FFMA2(acc, a, b) asm("fma.rn.f32x2 %0, %1, %2, %0;" : "+l"(acc) : "l"(a), "l"(b))

__global__ void rnn_init_kernel() {
    int idx = blockIdx.x * blockDim.x + threadIdx.x;
    int n = BATCH * UN;
    for (int i = idx; i < n; i += gridDim.x * blockDim.x) {
        g_h0[1][i] = 0.0f;   // read as h0_{-1} at p=0
        g_h1[1][i] = 0.0f;   // read as h1_{-1} at p=1
    }
    if (idx == 0) g_bar = 0u;
}

// Grid-wide barrier: all NCTA CTAs are co-resident (NCTA <= SM count, 1 CTA/SM).
__device__ __forceinline__ void gbar(unsigned int target) {
    __syncthreads();
    if (threadIdx.x == 0) {
        __threadfence();                         // release all prior global writes
        atomicAdd(&g_bar, 1u);
        unsigned int v;
        do {
            asm volatile("ld.acquire.gpu.u32 %0, [%1];" : "=r"(v) : "l"(&g_bar) : "memory");
        } while (v < target);
    }
    __syncthreads();
}

// Accumulate a K-chunk for up to two output tiles (A and B) sharing the same
// source-activation chunk hs. Each thread owns 4 rows (r0..r0+3) x 1 column.
// f32x2 packs (even_k, odd_k) partial sums; both h and W k-pairs are contiguous.
template <bool DA, bool DB>
__device__ __forceinline__ void gemm_chunk(int ck, int r0, int col,
    const float* __restrict__ hs, const float* __restrict__ wsA,
    const float* __restrict__ wsB, ull* accA, ull* accB)
{
    const float* wpa = wsA + col * WS_STRIDE;
    const float* wpb = wsB + col * WS_STRIDE;
    #pragma unroll 4
    for (int k = 0; k < ck; k += 4) {
        ulonglong2 h[4];
        #pragma unroll
        for (int j = 0; j < 4; j++)
            h[j] = *(const ulonglong2*)(hs + (r0 + j) * HS_STRIDE + k);
        if (DA) {
            ull wa0 = *(const ull*)(wpa + k);
            ull wa1 = *(const ull*)(wpa + k + 2);
            #pragma unroll
            for (int j = 0; j < 4; j++) {
                FFMA2(accA[j], h[j].x, wa0);
                FFMA2(accA[j], h[j].y, wa1);
            }
        }
        if (DB) {
            ull wb0 = *(const ull*)(wpb + k);
            ull wb1 = *(const ull*)(wpb + k + 2);
            #pragma unroll
            for (int j = 0; j < 4; j++) {
                FFMA2(accB[j], h[j].x, wb0);
                FFMA2(accB[j], h[j].y, wb1);
            }
        }
    }
}

extern __shared__ float smem[];

__global__ void __launch_bounds__(NTHR, 1) rnn_persistent(
    const int*   __restrict__ inputs, const float* __restrict__ emb,
    const float* __restrict__ Wx0,    const float* __restrict__ Wh0,
    const float* __restrict__ b0,     const float* __restrict__ Wx1,
    const float* __restrict__ Wh1,    const float* __restrict__ b1,
    const float* __restrict__ Wo,     const float* __restrict__ bo,
    float* __restrict__ out)
{
    float* hs  = smem;                                 // BATCH * HS_STRIDE
    float* wsA = smem + BATCH * HS_STRIDE;             // CPB * WS_STRIDE
    float* wsB = wsA + CPB * WS_STRIDE;                // CPB * WS_STRIDE

    const int tid  = threadIdx.x;
    const int col  = tid & (CPB - 1);
    const int r0   = (tid >> 4) << 2;                  // 4 rows per thread
    const int cb   = blockIdx.x * CPB;
    const int gcol = cb + col;
    const unsigned int nc = gridDim.x;

    // Phase p: tileA computes h0_p (needs h0_{p-1}, x_p); tileB computes h1_{p-1}
    // (needs h0_{p-1}, h1_{p-2}). Both depend only on phase p-1 state.
    for (int p = 0; p <= SEQT; ++p) {
        const bool doA = (p < SEQT);
        const bool doB = (p >= 1);
        ull accA[4] = {0ull, 0ull, 0ull, 0ull};
        ull accB[4] = {0ull, 0ull, 0ull, 0ull};
        const float* h0prev = g_h0[(p + 1) & 1];
        const float* h1prev = g_h1[p & 1];

        if (doA) {
            // ---- x_p @ Wx0 (K = 100), tile A only ----
            for (int i = tid; i < BATCH * (EMBD / 4); i += NTHR) {
                int row = i / (EMBD / 4), c4 = i % (EMBD / 4);
                int tok = __ldg(&inputs[row * SEQT + p]);
                *(float4*)(hs + row * HS_STRIDE + c4 * 4) =
                    *(const float4*)(emb + (size_t)tok * EMBD + c4 * 4);
            }
            for (int i = tid; i < CPB * EMBD; i += NTHR) {
                int c = i & (CPB - 1), k = i >> 4;
                wsA[c * WS_STRIDE + k] = Wx0[k * UN + cb + c];
            }
            __syncthreads();
            gemm_chunk<true, false>(EMBD, r0, col, hs, wsA, wsB, accA, accB);
            __syncthreads();
        }

        // ---- h0_{p-1} feeds BOTH tiles: A += h0p@Wh0, B += h0p@Wx1 ----
        for (int kc = 0; kc < UN; kc += CK) {
            for (int i = tid; i < BATCH * (CK / 4); i += NTHR) {
                int row = i >> 5, c4 = i & 31;
                *(float4*)(hs + row * HS_STRIDE + c4 * 4) =
                    *(const float4*)(h0prev + (size_t)row * UN + kc + c4 * 4);
            }
            if (doA)
                for (int i = tid; i < CPB * CK; i += NTHR) {
                    int c = i & (CPB - 1), k = i >> 4;
                    wsA[c * WS_STRIDE + k] = Wh0[(size_t)(kc + k) * UN + cb + c];
                }
            if (doB)
                for (int i = tid; i < CPB * CK; i += NTHR) {
                    int c = i & (CPB - 1), k = i >> 4;
                    wsB[c * WS_STRIDE + k] = Wx1[(size_t)(kc + k) * UN + cb + c];
                }
            __syncthreads();
            if (doA && doB)      gemm_chunk<true,  true >(CK, r0, col, hs, wsA, wsB, accA, accB);
            else if (doA)        gemm_chunk<true,  false>(CK, r0, col, hs, wsA, wsB, accA, accB);
            else                 gemm_chunk<false, true >(CK, r0, col, hs, wsA, wsB, accA, accB);
            __syncthreads();
        }

        // ---- h1_{p-2} @ Wh1, tile B only ----
        if (doB) {
            for (int kc = 0; kc < UN; kc += CK) {
                for (int i = tid; i < BATCH * (CK / 4); i += NTHR) {
                    int row = i >> 5, c4 = i & 31;
                    *(float4*)(hs + row * HS_STRIDE + c4 * 4) =
                        *(const float4*)(h1prev + (size_t)row * UN + kc + c4 * 4);
                }
                for (int i = tid; i < CPB * CK; i += NTHR) {
                    int c = i & (CPB - 1), k = i >> 4;
                    wsB[c * WS_STRIDE + k] = Wh1[(size_t)(kc + k) * UN + cb + c];
                }
                __syncthreads();
                gemm_chunk<false, true>(CK, r0, col, hs, wsA, wsB, accA, accB);
                __syncthreads();
            }
        }

        // ---- writeback: tanh(acc_even + acc_odd + bias) ----
        if (doA) {
            float bb = b0[gcol];
            float* dst = g_h0[p & 1];
            #pragma unroll
            for (int j = 0; j < 4; j++) {
                float vx = __uint_as_float((unsigned)(accA[j] & 0xffffffffull));
                float vy = __uint_as_float((unsigned)(accA[j] >> 32));
                dst[(size_t)(r0 + j) * UN + gcol] = tanhf(vx + vy + bb);
            }
        }
        if (doB) {
            float bb = b1[gcol];
            float* dst = g_h1[(p + 1) & 1];
            #pragma unroll
            for (int j = 0; j < 4; j++) {
                float vx = __uint_as_float((unsigned)(accB[j] & 0xffffffffull));
                float vy = __uint_as_float((unsigned)(accB[j] >> 32));
                dst[(size_t)(r0 + j) * UN + gcol] = tanhf(vx + vy + bb);
            }
        }
        gbar((unsigned)(p + 1) * nc);
    }

    // ---- final: out[b] = sigmoid(h1_{T-1}[b] . Wo + bo) ----
    if (blockIdx.x == 0) {
        const float* h1f = g_h1[(SEQT - 1) & 1];   // buffer 1
        const int warp = tid >> 5, lane = tid & 31;
        const float bof = bo[0];
        for (int r = warp; r < BATCH; r += NTHR / 32) {
            float s = 0.0f;
            for (int k = lane; k < UN; k += 32)
                s += h1f[(size_t)r * UN + k] * Wo[k];
            #pragma unroll
            for (int o = 16; o > 0; o >>= 1)
                s += __shfl_xor_sync(0xffffffffu, s, o);
            if (lane == 0)
                out[r] = 1.0f / (1.0f + expf(-(s + bof)));
        }
    }
}

extern "C" void kernel_launch(void* const* d_in, const int* in_sizes, int n_in,
                              void* d_out, int out_size)
{
    const int*   inputs = (const int*)  d_in[0];
    const float* emb    = (const float*)d_in[1];
    const float* Wx0    = (const float*)d_in[2];
    const float* Wh0    = (const float*)d_in[3];
    const float* b0     = (const float*)d_in[4];
    const float* Wx1    = (const float*)d_in[5];
    const float* Wh1    = (const float*)d_in[6];
    const float* b1     = (const float*)d_in[7];
    const float* Wo     = (const float*)d_in[8];
    const float* bo     = (const float*)d_in[9];
    float* out = (float*)d_out;

    const int smem_bytes = (BATCH * HS_STRIDE + 2 * CPB * WS_STRIDE) * (int)sizeof(float); // 49408
    cudaFuncSetAttribute(rnn_persistent, cudaFuncAttributeMaxDynamicSharedMemorySize, smem_bytes);

    rnn_init_kernel<<<256, 256>>>();
    rnn_persistent<<<NCTA, NTHR, smem_bytes>>>(inputs, emb, Wx0, Wh0, b0,
                                               Wx1, Wh1, b1, Wo, bo, out);
}

// round 2
// speedup vs baseline: 1.5156x; 1.5156x over previous
#include <cuda_runtime.h>
#include <cuda_bf16.h>

#define BATCH 64
#define SEQT  80
#define EMBD  100
#define UN    2048
#define NCTA  128
#define NTHR  512
#define CPB   16
#define CK    128
#define HST   132              // h smem row stride (floats), 16B aligned
#define WST   130              // w smem col stride (floats), conflict-free LDS.64
#define HSZ   (BATCH*HST)      // 8448 floats per h buffer
#define WSZ   (CPB*WST)        // 2080 floats per w buffer
#define NBUF  3

typedef unsigned long long ull;

__device__ float g_h0[2][BATCH * UN];
__device__ float g_h1[2][BATCH * UN];
__device__ unsigned int g_bar;

extern __shared__ float smem[];   // [NBUF*HSZ h][NBUF*2*WSZ w]

#define FFMA2(acc, a, b) asm("fma.rn.f32x2 %0, %1, %2, %0;" : "+l"(acc) : "l"(a), "l"(b))

__device__ __forceinline__ void cp16(float* d, const float* s) {
    unsigned ds = (unsigned)__cvta_generic_to_shared(d);
    asm volatile("cp.async.ca.shared.global [%0], [%1], 16;" :: "r"(ds), "l"(s));
}
__device__ __forceinline__ void cp4(float* d, const float* s) {
    unsigned ds = (unsigned)__cvta_generic_to_shared(d);
    asm volatile("cp.async.ca.shared.global [%0], [%1], 4;" :: "r"(ds), "l"(s));
}
#define CP_COMMIT() asm volatile("cp.async.commit_group;" ::: "memory")
#define CP_WAIT1()  asm volatile("cp.async.wait_group 1;" ::: "memory")
#define CP_WAIT0()  asm volatile("cp.async.wait_group 0;" ::: "memory")

__global__ void rnn_init_kernel() {
    int idx = blockIdx.x * blockDim.x + threadIdx.x;
    for (int i = idx; i < BATCH * UN; i += gridDim.x * blockDim.x) {
        g_h0[1][i] = 0.0f;
        g_h1[1][i] = 0.0f;
    }
    if (idx == 0) g_bar = 0u;
}

// Grid barrier: all NCTA CTAs co-resident (NCTA <= 148, 1 CTA/SM).
__device__ __forceinline__ void gbar(unsigned int target) {
    __syncthreads();
    if (threadIdx.x == 0) {
        __threadfence();
        atomicAdd(&g_bar, 1u);
        unsigned int v;
        do {
            asm volatile("ld.acquire.gpu.u32 %0, [%1];" : "=r"(v) : "l"(&g_bar) : "memory");
        } while (v < target);
    }
    __syncthreads();
}

// Stage one K-chunk (h activations + transposed weight slabs) into buffer b.
// type 0: embedding (tile A, zero-padded K 100->128)
// type 1: h0 chunk (A: Wh0, B: Wx1)     type 2: h1 chunk (B: Wh1)
__device__ __forceinline__ void stage_chunk(
    int type, int kc, int p, int b, bool dA, bool dB,
    const int* __restrict__ inputs, const float* __restrict__ emb,
    const float* __restrict__ Wx0, const float* __restrict__ Wh0,
    const float* __restrict__ Wx1, const float* __restrict__ Wh1,
    const float* __restrict__ h0prev, const float* __restrict__ h1prev,
    int cb, int tid)
{
    float* hs = smem + b * HSZ;
    float* wA = smem + NBUF * HSZ + b * (2 * WSZ);
    float* wB = wA + WSZ;
    if (type == 0) {
        for (int i = tid; i < BATCH * 25; i += NTHR) {       // 100 floats = 25 f4
            int row = i / 25, c4 = i % 25;
            int tok = __ldg(&inputs[row * SEQT + p]);
            cp16(hs + row * HST + c4 * 4, emb + (size_t)tok * EMBD + c4 * 4);
        }
        float4 z = make_float4(0.f, 0.f, 0.f, 0.f);
        for (int i = tid; i < BATCH * 7; i += NTHR) {        // pad k 100..127
            int row = i / 7, c4 = 25 + i % 7;
            *(float4*)(hs + row * HST + c4 * 4) = z;
        }
        for (int i = tid; i < CPB * CK; i += NTHR) {
            int c = i & 15, k = i >> 4;
            if (k < EMBD) cp4(wA + c * WST + k, Wx0 + (size_t)k * UN + cb + c);
            else          wA[c * WST + k] = 0.f;
        }
    } else if (type == 1) {
        for (int i = tid; i < BATCH * 32; i += NTHR) {
            int row = i >> 5, c4 = i & 31;
            cp16(hs + row * HST + c4 * 4, h0prev + (size_t)row * UN + kc + c4 * 4);
        }
        if (dA)
            for (int i = tid; i < CPB * CK; i += NTHR) {
                int c = i & 15, k = i >> 4;
                cp4(wA + c * WST + k, Wh0 + (size_t)(kc + k) * UN + cb + c);
            }
        if (dB)
            for (int i = tid; i < CPB * CK; i += NTHR) {
                int c = i & 15, k = i >> 4;
                cp4(wB + c * WST + k, Wx1 + (size_t)(kc + k) * UN + cb + c);
            }
    } else {
        for (int i = tid; i < BATCH * 32; i += NTHR) {
            int row = i >> 5, c4 = i & 31;
            cp16(hs + row * HST + c4 * 4, h1prev + (size_t)row * UN + kc + c4 * 4);
        }
        for (int i = tid; i < CPB * CK; i += NTHR) {
            int c = i & 15, k = i >> 4;
            cp4(wB + c * WST + k, Wh1 + (size_t)(kc + k) * UN + cb + c);
        }
    }
}

// Compute this thread's 32-k slice of buffer b: 4 rows x 2 cols per tile.
template <bool CA, bool CB>
__device__ __forceinline__ void gemm32(int b, int kq, int r0, int c0,
                                       ull accA[4][2], ull accB[4][2])
{
    const float* hs = smem + b * HSZ;
    const float* wA = smem + NBUF * HSZ + b * (2 * WSZ);
    const float* wB = wA + WSZ;
    const int kb = kq * 32;
    #pragma unroll
    for (int kk = 0; kk < 32; kk += 4) {
        const int k = kb + kk;
        ulonglong2 h[4];
        #pragma unroll
        for (int j = 0; j < 4; j++)
            h[j] = *(const ulonglong2*)(hs + (r0 + j) * HST + k);
        if (CA) {
            #pragma unroll
            for (int cc = 0; cc < 2; cc++) {
                const float* wp = wA + (c0 + cc) * WST + k;
                ull w0 = *(const ull*)wp, w1 = *(const ull*)(wp + 2);
                #pragma unroll
                for (int j = 0; j < 4; j++) {
                    FFMA2(accA[j][cc], h[j].x, w0);
                    FFMA2(accA[j][cc], h[j].y, w1);
                }
            }
        }
        if (CB) {
            #pragma unroll
            for (int cc = 0; cc < 2; cc++) {
                const float* wp = wB + (c0 + cc) * WST + k;
                ull w0 = *(const ull*)wp, w1 = *(const ull*)(wp + 2);
                #pragma unroll
                for (int j = 0; j < 4; j++) {
                    FFMA2(accB[j][cc], h[j].x, w0);
                    FFMA2(accB[j][cc], h[j].y, w1);
                }
            }
        }
    }
}

__global__ void __launch_bounds__(NTHR, 1) rnn_persistent(
    const int*   __restrict__ inputs, const float* __restrict__ emb,
    const float* __restrict__ Wx0,    const float* __restrict__ Wh0,
    const float* __restrict__ b0,     const float* __restrict__ Wx1,
    const float* __restrict__ Wh1,    const float* __restrict__ b1,
    const float* __restrict__ Wo,     const float* __restrict__ bo,
    float* __restrict__ out)
{
    const int tid = threadIdx.x;
    const int kq  = tid >> 7;          // k-quarter 0..3
    const int t   = tid & 127;
    const int cg  = t & 7, rg = t >> 3;
    const int r0  = rg * 4, c0 = cg * 2;
    const int cb  = blockIdx.x * CPB;
    const unsigned int nc = gridDim.x;
    const int nh0 = UN / CK;           // 16

    for (int p = 0; p <= SEQT; ++p) {
        const bool dA = (p < SEQT);
        const bool dB = (p >= 1);
        const float* h0prev = g_h0[(p + 1) & 1];
        const float* h1prev = g_h1[p & 1];
        ull accA[4][2] = {}, accB[4][2] = {};

        const int nch = (dA ? 1 : 0) + nh0 + (dB ? nh0 : 0);
        // decode chunk index -> (type, kc)
        auto decode = [&](int ci, int& ty, int& kc) {
            int x = ci;
            if (dA) { if (x == 0) { ty = 0; kc = 0; return; } x--; }
            if (x < nh0) { ty = 1; kc = x * CK; return; }
            ty = 2; kc = (x - nh0) * CK;
        };

        int ty, kc;
        decode(0, ty, kc);
        stage_chunk(ty, kc, p, 0, dA, dB, inputs, emb, Wx0, Wh0, Wx1, Wh1,
                    h0prev, h1prev, cb, tid);
        CP_COMMIT();

        for (int g = 0; g < nch; ++g) {
            if (g + 1 < nch) {
                decode(g + 1, ty, kc);
                stage_chunk(ty, kc, p, (g + 1) % NBUF, dA, dB, inputs, emb,
                            Wx0, Wh0, Wx1, Wh1, h0prev, h1prev, cb, tid);
                CP_COMMIT();
                CP_WAIT1();
            } else {
                CP_WAIT0();
            }
            __syncthreads();
            int ty0, kc0; decode(g, ty0, kc0);
            const int b = g % NBUF;
            if (ty0 == 0)      gemm32<true,  false>(b, kq, r0, c0, accA, accB);
            else if (ty0 == 1) {
                if (dA && dB)  gemm32<true,  true >(b, kq, r0, c0, accA, accB);
                else if (dA)   gemm32<true,  false>(b, kq, r0, c0, accA, accB);
                else           gemm32<false, true >(b, kq, r0, c0, accA, accB);
            } else             gemm32<false, true >(b, kq, r0, c0, accA, accB);
        }

        // ---- K-split reduction (4 partials) + activation + writeback ----
        __syncthreads();                    // all computes done; reuse h buffers
        float* red = smem;                  // 512*16 floats = 32KB
        float v[16];
        #pragma unroll
        for (int j = 0; j < 4; j++)
            #pragma unroll
            for (int cc = 0; cc < 2; cc++) {
                ull a = accA[j][cc], bq = accB[j][cc];
                v[j * 2 + cc]     = __uint_as_float((unsigned)(a & 0xffffffffull)) +
                                    __uint_as_float((unsigned)(a >> 32));
                v[8 + j * 2 + cc] = __uint_as_float((unsigned)(bq & 0xffffffffull)) +
                                    __uint_as_float((unsigned)(bq >> 32));
            }
        #pragma unroll
        for (int q = 0; q < 4; q++)
            *(float4*)(red + tid * 16 + q * 4) =
                make_float4(v[q * 4], v[q * 4 + 1], v[q * 4 + 2], v[q * 4 + 3]);
        __syncthreads();

        if (kq == 0) {
            #pragma unroll
            for (int idx = 0; idx < 16; idx++) {
                float s = red[t * 16 + idx] + red[(t + 128) * 16 + idx] +
                          red[(t + 256) * 16 + idx] + red[(t + 384) * 16 + idx];
                int loc = (idx < 8) ? idx : idx - 8;
                int j = loc >> 1, cc = loc & 1;
                int gc = cb + c0 + cc;
                if (idx < 8) {
                    if (dA) g_h0[p & 1][(size_t)(r0 + j) * UN + gc] = tanhf(s + b0[gc]);
                } else {
                    if (dB) g_h1[(p + 1) & 1][(size_t)(r0 + j) * UN + gc] = tanhf(s + b1[gc]);
                }
            }
        }
        gbar((unsigned)(p + 1) * nc);
    }

    // ---- final: out[b] = sigmoid(h1_{T-1} . Wo + bo) ----
    if (blockIdx.x == 0) {
        const float* h1f = g_h1[(SEQT - 1) & 1];
        const int warp = tid >> 5, lane = tid & 31;
        const float bof = bo[0];
        for (int r = warp; r < BATCH; r += NTHR / 32) {
            float s = 0.0f;
            for (int k = lane; k < UN; k += 32)
                s += h1f[(size_t)r * UN + k] * Wo[k];
            #pragma unroll
            for (int o = 16; o > 0; o >>= 1)
                s += __shfl_xor_sync(0xffffffffu, s, o);
            if (lane == 0)
                out[r] = 1.0f / (1.0f + expf(-(s + bof)));
        }
    }
}

extern "C" void kernel_launch(void* const* d_in, const int* in_sizes, int n_in,
                              void* d_out, int out_size)
{
    const int*   inputs = (const int*)  d_in[0];
    const float* emb    = (const float*)d_in[1];
    const float* Wx0    = (const float*)d_in[2];
    const float* Wh0    = (const float*)d_in[3];
    const float* b0     = (const float*)d_in[4];
    const float* Wx1    = (const float*)d_in[5];
    const float* Wh1    = (const float*)d_in[6];
    const float* b1     = (const float*)d_in[7];
    const float* Wo     = (const float*)d_in[8];
    const float* bo     = (const float*)d_in[9];
    float* out = (float*)d_out;

    const int smem_bytes = (NBUF * HSZ + NBUF * 2 * WSZ) * (int)sizeof(float); // 151296
    cudaFuncSetAttribute(rnn_persistent, cudaFuncAttributeMaxDynamicSharedMemorySize, smem_bytes);

    rnn_init_kernel<<<256, 256>>>();
    rnn_persistent<<<NCTA, NTHR, smem_bytes>>>(inputs, emb, Wx0, Wh0, b0,
                                               Wx1, Wh1, b1, Wo, bo, out);
}

// round 3
// speedup vs baseline: 1.6525x; 1.0903x over previous
#include <cuda_runtime.h>
#include <cuda_bf16.h>

#define BATCH 64
#define SEQT  80
#define EMBD  100
#define KPAD  128
#define UN    2048
#define NCTA  128
#define NTHR  512
#define CPB   16
#define CK    128
#define HST   132              // h smem row stride (floats)
#define WST   132              // w smem col stride (floats), 16B-aligned cols
#define HSZ   (BATCH*HST)      // 8448 floats
#define WSZ   (CPB*WST)        // 2112 floats
#define NBUF  3

typedef unsigned long long ull;

__device__ float g_h0[2][BATCH * UN];
__device__ float g_h1[2][BATCH * UN];
__device__ unsigned int g_bar;
// Pre-transposed weights: WT[n][k] = W[k][n]
__device__ float g_Wh0T[UN * UN];
__device__ float g_Wx1T[UN * UN];
__device__ float g_Wh1T[UN * UN];
__device__ float g_Wx0T[UN * KPAD];   // K padded 100 -> 128 with zeros

extern __shared__ float smem[];

#define FFMA2(acc, a, b) asm("fma.rn.f32x2 %0, %1, %2, %0;" : "+l"(acc) : "l"(a), "l"(b))

__device__ __forceinline__ void cp16(float* d, const float* s) {
    unsigned ds = (unsigned)__cvta_generic_to_shared(d);
    asm volatile("cp.async.ca.shared.global [%0], [%1], 16;" :: "r"(ds), "l"(s));
}
#define CP_COMMIT() asm volatile("cp.async.commit_group;" ::: "memory")
#define CP_WAIT1()  asm volatile("cp.async.wait_group 1;" ::: "memory")
#define CP_WAIT0()  asm volatile("cp.async.wait_group 0;" ::: "memory")

__global__ void rnn_init_kernel() {
    int idx = blockIdx.x * blockDim.x + threadIdx.x;
    for (int i = idx; i < BATCH * UN; i += gridDim.x * blockDim.x) {
        g_h0[1][i] = 0.0f;
        g_h1[1][i] = 0.0f;
    }
    if (idx == 0) g_bar = 0u;
}

// dst[n][kpad] = (k < K) ? src[k][n] : 0
__global__ void transpose_pad(const float* __restrict__ src, float* __restrict__ dst,
                              int K, int N, int Kpad) {
    __shared__ float tile[32][33];
    int kb = blockIdx.y * 32, nb = blockIdx.x * 32;
    int tx = threadIdx.x, ty = threadIdx.y;
    #pragma unroll
    for (int j = 0; j < 32; j += 8) {
        int k = kb + ty + j, n = nb + tx;
        tile[ty + j][tx] = (k < K && n < N) ? src[(size_t)k * N + n] : 0.0f;
    }
    __syncthreads();
    #pragma unroll
    for (int j = 0; j < 32; j += 8) {
        int n = nb + ty + j, k = kb + tx;
        if (n < N && k < Kpad) dst[(size_t)n * Kpad + k] = tile[tx][ty + j];
    }
}

__device__ __forceinline__ void gbar(unsigned int target) {
    __syncthreads();
    if (threadIdx.x == 0) {
        __threadfence();
        atomicAdd(&g_bar, 1u);
        unsigned int v;
        do {
            asm volatile("ld.acquire.gpu.u32 %0, [%1];" : "=r"(v) : "l"(&g_bar) : "memory");
        } while (v < target);
    }
    __syncthreads();
}

// Stage one K-chunk into buffer b.
// type 0: emb -> hs (pad 100..127), Wx0T slab -> wA
// type 1: h0prev -> hs, Wh0T -> wA (if dA), Wx1T -> wB (if dB)
// type 2: h1prev -> hs, Wh1T -> wB
__device__ __forceinline__ void stage_chunk(
    int type, int kc, int p, int b, bool dA, bool dB,
    const int* __restrict__ inputs, const float* __restrict__ emb,
    const float* __restrict__ h0prev, const float* __restrict__ h1prev,
    int cb, int tid)
{
    float* hs = smem + b * HSZ;
    float* wA = smem + NBUF * HSZ + b * (2 * WSZ);
    float* wB = wA + WSZ;
    if (type == 0) {
        for (int i = tid; i < BATCH * 25; i += NTHR) {
            int row = i / 25, c4 = i % 25;
            int tok = __ldg(&inputs[row * SEQT + p]);
            cp16(hs + row * HST + c4 * 4, emb + (size_t)tok * EMBD + c4 * 4);
        }
        float4 z = make_float4(0.f, 0.f, 0.f, 0.f);
        for (int i = tid; i < BATCH * 7; i += NTHR) {
            int row = i / 7, c4 = 25 + i % 7;
            *(float4*)(hs + row * HST + c4 * 4) = z;
        }
        for (int i = tid; i < CPB * 32; i += NTHR) {
            int c = i >> 5, q = i & 31;
            cp16(wA + c * WST + q * 4, g_Wx0T + (size_t)(cb + c) * KPAD + q * 4);
        }
    } else if (type == 1) {
        for (int i = tid; i < BATCH * 32; i += NTHR) {
            int row = i >> 5, c4 = i & 31;
            cp16(hs + row * HST + c4 * 4, h0prev + (size_t)row * UN + kc + c4 * 4);
        }
        if (dA)
            for (int i = tid; i < CPB * 32; i += NTHR) {
                int c = i >> 5, q = i & 31;
                cp16(wA + c * WST + q * 4, g_Wh0T + (size_t)(cb + c) * UN + kc + q * 4);
            }
        if (dB)
            for (int i = tid; i < CPB * 32; i += NTHR) {
                int c = i >> 5, q = i & 31;
                cp16(wB + c * WST + q * 4, g_Wx1T + (size_t)(cb + c) * UN + kc + q * 4);
            }
    } else {
        for (int i = tid; i < BATCH * 32; i += NTHR) {
            int row = i >> 5, c4 = i & 31;
            cp16(hs + row * HST + c4 * 4, h1prev + (size_t)row * UN + kc + c4 * 4);
        }
        for (int i = tid; i < CPB * 32; i += NTHR) {
            int c = i >> 5, q = i & 31;
            cp16(wB + c * WST + q * 4, g_Wh1T + (size_t)(cb + c) * UN + kc + q * 4);
        }
    }
}

// Compute 32-k slice: 4 rows (o+16j) x 2 cols (cg, cg+8) per tile.
template <bool CA, bool CB>
__device__ __forceinline__ void gemm32(int b, int kq, int o, int cg,
                                       ull accA[4][2], ull accB[4][2])
{
    const float* hs = smem + b * HSZ;
    const float* wA = smem + NBUF * HSZ + b * (2 * WSZ);
    const float* wB = wA + WSZ;
    const int kb = kq * 32;
    #pragma unroll
    for (int kk = 0; kk < 32; kk += 4) {
        const int k = kb + kk;
        ulonglong2 h[4];
        #pragma unroll
        for (int j = 0; j < 4; j++)
            h[j] = *(const ulonglong2*)(hs + (o + 16 * j) * HST + k);
        if (CA) {
            #pragma unroll
            for (int cc = 0; cc < 2; cc++) {
                ulonglong2 w = *(const ulonglong2*)(wA + (cg + 8 * cc) * WST + k);
                #pragma unroll
                for (int j = 0; j < 4; j++) {
                    FFMA2(accA[j][cc], h[j].x, w.x);
                    FFMA2(accA[j][cc], h[j].y, w.y);
                }
            }
        }
        if (CB) {
            #pragma unroll
            for (int cc = 0; cc < 2; cc++) {
                ulonglong2 w = *(const ulonglong2*)(wB + (cg + 8 * cc) * WST + k);
                #pragma unroll
                for (int j = 0; j < 4; j++) {
                    FFMA2(accB[j][cc], h[j].x, w.x);
                    FFMA2(accB[j][cc], h[j].y, w.y);
                }
            }
        }
    }
}

__global__ void __launch_bounds__(NTHR, 1) rnn_persistent(
    const int*   __restrict__ inputs, const float* __restrict__ emb,
    const float* __restrict__ b0,     const float* __restrict__ b1,
    const float* __restrict__ Wo,     const float* __restrict__ bo,
    float* __restrict__ out)
{
    const int tid = threadIdx.x;
    const int kq  = tid >> 7;
    const int t   = tid & 127;
    const int cg  = t & 7;             // cols cg, cg+8
    const int o   = t >> 3;            // rows o + 16j
    const int cb  = blockIdx.x * CPB;
    const unsigned int nc = gridDim.x;
    const int nh0 = UN / CK;           // 16

    for (int p = 0; p <= SEQT; ++p) {
        const bool dA = (p < SEQT);
        const bool dB = (p >= 1);
        const float* h0prev = g_h0[(p + 1) & 1];
        const float* h1prev = g_h1[p & 1];
        ull accA[4][2] = {}, accB[4][2] = {};

        const int nch = (dA ? 1 : 0) + nh0 + (dB ? nh0 : 0);
        auto decode = [&](int ci, int& ty, int& kc) {
            int x = ci;
            if (dA) { if (x == 0) { ty = 0; kc = 0; return; } x--; }
            if (x < nh0) { ty = 1; kc = x * CK; return; }
            ty = 2; kc = (x - nh0) * CK;
        };

        int ty, kc;
        decode(0, ty, kc);
        stage_chunk(ty, kc, p, 0, dA, dB, inputs, emb, h0prev, h1prev, cb, tid);
        CP_COMMIT();

        for (int g = 0; g < nch; ++g) {
            if (g + 1 < nch) {
                decode(g + 1, ty, kc);
                stage_chunk(ty, kc, p, (g + 1) % NBUF, dA, dB, inputs, emb,
                            h0prev, h1prev, cb, tid);
                CP_COMMIT();
                CP_WAIT1();
            } else {
                CP_WAIT0();
            }
            __syncthreads();
            int ty0, kc0; decode(g, ty0, kc0);
            const int b = g % NBUF;
            if (ty0 == 0)      gemm32<true,  false>(b, kq, o, cg, accA, accB);
            else if (ty0 == 1) {
                if (dA && dB)  gemm32<true,  true >(b, kq, o, cg, accA, accB);
                else if (dA)   gemm32<true,  false>(b, kq, o, cg, accA, accB);
                else           gemm32<false, true >(b, kq, o, cg, accA, accB);
            } else             gemm32<false, true >(b, kq, o, cg, accA, accB);
        }

        // ---- K-split reduction (4 partials) + activation + writeback ----
        __syncthreads();
        float* red = smem;                  // 512*16 floats = 32KB (h buf 0)
        float v[16];
        #pragma unroll
        for (int j = 0; j < 4; j++)
            #pragma unroll
            for (int cc = 0; cc < 2; cc++) {
                ull a = accA[j][cc], bq = accB[j][cc];
                v[j * 2 + cc]     = __uint_as_float((unsigned)(a & 0xffffffffull)) +
                                    __uint_as_float((unsigned)(a >> 32));
                v[8 + j * 2 + cc] = __uint_as_float((unsigned)(bq & 0xffffffffull)) +
                                    __uint_as_float((unsigned)(bq >> 32));
            }
        #pragma unroll
        for (int q = 0; q < 4; q++)
            *(float4*)(red + tid * 16 + q * 4) =
                make_float4(v[q * 4], v[q * 4 + 1], v[q * 4 + 2], v[q * 4 + 3]);
        __syncthreads();

        if (kq == 0) {
            #pragma unroll
            for (int idx = 0; idx < 16; idx++) {
                float s = red[t * 16 + idx] + red[(t + 128) * 16 + idx] +
                          red[(t + 256) * 16 + idx] + red[(t + 384) * 16 + idx];
                int loc = (idx < 8) ? idx : idx - 8;
                int j = loc >> 1, cc = loc & 1;
                int r = o + 16 * j;
                int gc = cb + cg + 8 * cc;
                if (idx < 8) {
                    if (dA) g_h0[p & 1][(size_t)r * UN + gc] = tanhf(s + b0[gc]);
                } else {
                    if (dB) g_h1[(p + 1) & 1][(size_t)r * UN + gc] = tanhf(s + b1[gc]);
                }
            }
        }
        gbar((unsigned)(p + 1) * nc);
    }

    // ---- final: out[b] = sigmoid(h1_{T-1} . Wo + bo) ----
    if (blockIdx.x == 0) {
        const float* h1f = g_h1[(SEQT - 1) & 1];
        const int warp = tid >> 5, lane = tid & 31;
        const float bof = bo[0];
        for (int r = warp; r < BATCH; r += NTHR / 32) {
            float s = 0.0f;
            for (int k = lane; k < UN; k += 32)
                s += h1f[(size_t)r * UN + k] * Wo[k];
            #pragma unroll
            for (int off = 16; off > 0; off >>= 1)
                s += __shfl_xor_sync(0xffffffffu, s, off);
            if (lane == 0)
                out[r] = 1.0f / (1.0f + expf(-(s + bof)));
        }
    }
}

extern "C" void kernel_launch(void* const* d_in, const int* in_sizes, int n_in,
                              void* d_out, int out_size)
{
    const int*   inputs = (const int*)  d_in[0];
    const float* emb    = (const float*)d_in[1];
    const float* Wx0    = (const float*)d_in[2];
    const float* Wh0    = (const float*)d_in[3];
    const float* b0     = (const float*)d_in[4];
    const float* Wx1    = (const float*)d_in[5];
    const float* Wh1    = (const float*)d_in[6];
    const float* b1     = (const float*)d_in[7];
    const float* Wo     = (const float*)d_in[8];
    const float* bo     = (const float*)d_in[9];
    float* out = (float*)d_out;

    float* wh0t; cudaGetSymbolAddress((void**)&wh0t, g_Wh0T);
    float* wx1t; cudaGetSymbolAddress((void**)&wx1t, g_Wx1T);
    float* wh1t; cudaGetSymbolAddress((void**)&wh1t, g_Wh1T);
    float* wx0t; cudaGetSymbolAddress((void**)&wx0t, g_Wx0T);

    dim3 tb(32, 8);
    transpose_pad<<<dim3(UN / 32, UN / 32), tb>>>(Wh0, wh0t, UN, UN, UN);
    transpose_pad<<<dim3(UN / 32, UN / 32), tb>>>(Wx1, wx1t, UN, UN, UN);
    transpose_pad<<<dim3(UN / 32, UN / 32), tb>>>(Wh1, wh1t, UN, UN, UN);
    transpose_pad<<<dim3(UN / 32, KPAD / 32), tb>>>(Wx0, wx0t, EMBD, UN, KPAD);

    const int smem_bytes = (NBUF * HSZ + NBUF * 2 * WSZ) * (int)sizeof(float); // 152064
    cudaFuncSetAttribute(rnn_persistent, cudaFuncAttributeMaxDynamicSharedMemorySize, smem_bytes);

    rnn_init_kernel<<<256, 256>>>();
    rnn_persistent<<<NCTA, NTHR, smem_bytes>>>(inputs, emb, b0, b1, Wo, bo, out);
}